// round 15
// baseline (speedup 1.0000x reference)
#include <cuda_runtime.h>
#include <cuda_fp16.h>

#define NUSER 150000
#define NITEM 75000
#define NTOT  225000
#define DD    64
#define NNZV  2000000
#define VSCALE 0.01f

// ---------------- static device scratch ----------------
__device__ int   g_cnt[NTOT];
__device__ int   g_inc[NTOT];
__device__ int   g_bsum[256];
__device__ int   g_rowptr[NTOT + 1];
__device__ int   g_wptr[NTOT + 1];
__device__ int2  g_edge[NNZV];                    // {col, val-as-int}
__device__ __half2 g_x0[(size_t)NTOT * 32];       // fused user+item, fp16
__device__ __half2 g_h1[(size_t)NTOT * 32];
__device__ __half2 g_h2[(size_t)NTOT * 32];

// ---------------- fused: histogram (first nbE blocks) + fp16 convert --------
__global__ void k_hist_convert(const int* __restrict__ rows,
                               const float2* __restrict__ user,
                               const float2* __restrict__ item,
                               int nbE) {
    if ((int)blockIdx.x < nbE) {
        int e = blockIdx.x * blockDim.x + threadIdx.x;
        if (e < NNZV) atomicAdd(&g_cnt[__ldcs(rows + e)], 1);
    } else {
        int base = (blockIdx.x - nbE) * blockDim.x * 4 + threadIdx.x;
#pragma unroll
        for (int u = 0; u < 4; u++) {
            int i = base + u * blockDim.x;
            if (i < NTOT * 32) {
                float2 v = (i < NUSER * 32) ? __ldcs(user + i)
                                            : __ldcs(item + (i - NUSER * 32));
                g_x0[i] = __floats2half2_rn(v.x, v.y);
            }
        }
    }
}

// shfl-based block scan, 1024 threads, 2 barriers
__global__ void k_scan1() {
    __shared__ int wsum[32];
    int tid = threadIdx.x;
    int lane = tid & 31;
    int wp = tid >> 5;
    int i = blockIdx.x * 1024 + tid;
    int v = (i < NTOT) ? g_cnt[i] : 0;
#pragma unroll
    for (int off = 1; off < 32; off <<= 1) {
        int t = __shfl_up_sync(0xffffffffu, v, off);
        if (lane >= off) v += t;
    }
    if (lane == 31) wsum[wp] = v;
    __syncthreads();
    if (wp == 0) {
        int s = wsum[lane];
#pragma unroll
        for (int off = 1; off < 32; off <<= 1) {
            int t = __shfl_up_sync(0xffffffffu, s, off);
            if (lane >= off) s += t;
        }
        wsum[lane] = s;
    }
    __syncthreads();
    if (wp > 0) v += wsum[wp - 1];
    if (i < NTOT) g_inc[i] = v;
    if (tid == 1023) g_bsum[blockIdx.x] = v;
}

// merged scan2+scan3: each block (256 thr) shares one 1024-bucket; warp 0
// computes the exclusive prefix of g_bsum over [0, bucket) itself.
__global__ void k_scan23() {
    __shared__ int s_off;
    int tid = threadIdx.x;
    int i = blockIdx.x * 256 + tid;
    int bucket = (blockIdx.x * 256) >> 10;     // same for whole block
    if (tid < 32) {
        int acc = 0;
        for (int j = tid; j < bucket; j += 32) acc += g_bsum[j];
#pragma unroll
        for (int off = 16; off > 0; off >>= 1)
            acc += __shfl_down_sync(0xffffffffu, acc, off);
        if (tid == 0) s_off = acc;
    }
    __syncthreads();
    if (i < NTOT) {
        int val = g_inc[i] + s_off;
        g_rowptr[i + 1] = val;
        g_wptr[i + 1] = val;
        if (i == 0) { g_rowptr[0] = 0; g_wptr[0] = 0; }
    }
}

// ---------------- scatter (pure) ----------------
__global__ void k_scatter(const int* __restrict__ rows,
                          const int* __restrict__ cols,
                          const float* __restrict__ vals) {
    int e = blockIdx.x * blockDim.x + threadIdx.x;
    if (e < NNZV) {
        int r = __ldcs(rows + e);
        int p = atomicAdd(&g_wptr[r], 1);
        g_edge[p] = make_int2(__ldcs(cols + e),
                              __float_as_int(__ldcs(vals + e)));
    }
}

// ---------------- SpMM layers 1-2: 4 rows per warp, interleaved ----------
__global__ void k_spmm(const __half2* __restrict__ x,
                       __half2* __restrict__ y) {
    int lane = threadIdx.x & 31;
    int warp = threadIdx.x >> 5;
    int wid = blockIdx.x * 8 + warp;
    int row0 = wid * 4;
    if (row0 >= NTOT) return;
    const __half2* xlane = x + lane;

    int4 rp = *reinterpret_cast<const int4*>(&g_rowptr[row0]);
    int r4 = g_rowptr[row0 + 4];
    int p[4] = {rp.x, rp.y, rp.z, rp.w};
    int e[4] = {rp.y, rp.z, rp.w, r4};
    int maxlen = max(max(e[0] - p[0], e[1] - p[1]),
                     max(e[2] - p[2], e[3] - p[3]));

    float ax[4] = {0.f, 0.f, 0.f, 0.f};
    float ay[4] = {0.f, 0.f, 0.f, 0.f};

    for (int it = 0; it < maxlen; it++) {
#pragma unroll
        for (int i = 0; i < 4; i++) {
            int idx = p[i] + it;
            if (idx < e[i]) {
                int2 q = *reinterpret_cast<const int2*>(&g_edge[idx]);
                float vv = __int_as_float(q.y);
                float2 xv = __half22float2(__ldg(xlane + (size_t)q.x * 32));
                ax[i] += vv * xv.x;
                ay[i] += vv * xv.y;
            }
        }
    }

#pragma unroll
    for (int i = 0; i < 4; i++)
        y[(size_t)(row0 + i) * 32 + lane] = __floats2half2_rn(ax[i], ay[i]);
}

// ---------------- fused SpMM layer 3 + epilogue -----------------------------
__global__ void k_spmm3_epi(const __half2* __restrict__ h1,
                            const __half2* __restrict__ h2,
                            const float* __restrict__ W,
                            const float* __restrict__ bias,
                            const float2* __restrict__ n1,
                            const float2* __restrict__ n2,
                            float2* __restrict__ out_mean,
                            float2* __restrict__ out_std,
                            float2* __restrict__ out_v1,
                            float2* __restrict__ out_v2) {
    __shared__ float2 Ws[64 * 32];   // Ws[d*32+l] = {W[d][2l], W[d][2l+1]}
    for (int i = threadIdx.x; i < 64 * 32; i += blockDim.x) {
        int d = i >> 5, l = i & 31;
        Ws[i] = *reinterpret_cast<const float2*>(W + d * 64 + 2 * l);
    }
    __syncthreads();

    int lane = threadIdx.x & 31;
    int warp = threadIdx.x >> 5;
    int wid = blockIdx.x * 8 + warp;
    int row0 = wid * 4;
    if (row0 >= NTOT) return;
    const __half2* xlane = h2 + lane;

    // L2-prefetch the cold noise streams consumed after the gather loop.
    // Address-only instructions: no registers, no scoreboard dependencies.
#pragma unroll
    for (int r = 0; r < 4; r++) {
        const float2* pa = n1 + (size_t)(row0 + r) * 32 + lane;
        const float2* pb = n2 + (size_t)(row0 + r) * 32 + lane;
        asm volatile("prefetch.global.L2 [%0];" :: "l"(pa));
        asm volatile("prefetch.global.L2 [%0];" :: "l"(pb));
    }

    int4 rp = *reinterpret_cast<const int4*>(&g_rowptr[row0]);
    int r4 = g_rowptr[row0 + 4];
    int p[4] = {rp.x, rp.y, rp.z, rp.w};
    int e[4] = {rp.y, rp.z, rp.w, r4};
    int maxlen = max(max(e[0] - p[0], e[1] - p[1]),
                     max(e[2] - p[2], e[3] - p[3]));

    float ax[4] = {0.f, 0.f, 0.f, 0.f};
    float ay[4] = {0.f, 0.f, 0.f, 0.f};
    for (int it = 0; it < maxlen; it++) {
#pragma unroll
        for (int i = 0; i < 4; i++) {
            int idx = p[i] + it;
            if (idx < e[i]) {
                int2 q = *reinterpret_cast<const int2*>(&g_edge[idx]);
                float vv = __int_as_float(q.y);
                float2 xv = __half22float2(__ldg(xlane + (size_t)q.x * 32));
                ax[i] += vv * xv.x;
                ay[i] += vv * xv.y;
            }
        }
    }

    // ---- noise loads (should now be L2 hits) ----
    float2 na[4], nc[4];
#pragma unroll
    for (int r = 0; r < 4; r++) {
        size_t ix = (size_t)(row0 + r) * 32 + lane;
        na[r] = __ldcs(n1 + ix);
        nc[r] = __ldcs(n2 + ix);
    }

    // ---- mean (store immediately) ----
    float2 b = __ldg(reinterpret_cast<const float2*>(bias) + lane);
    float m0[4], m1[4], ls0[4], ls1[4];
#pragma unroll
    for (int r = 0; r < 4; r++) {
        size_t ix = (size_t)(row0 + r) * 32 + lane;
        float2 a1 = __half22float2(__ldg(h1 + ix));
        float2 a2 = __half22float2(__ldg(h2 + ix));
        m0[r] = (a1.x + a2.x + ax[r]) * (1.f / 3.f);
        m1[r] = (a1.y + a2.y + ay[r]) * (1.f / 3.f);
        __stcs(out_mean + ix, make_float2(m0[r], m1[r]));
        ls0[r] = b.x;
        ls1[r] = b.y;
    }

    // ---- 64x64 GEMM via shfl ----
#pragma unroll 4
    for (int dd = 0; dd < 32; dd++) {
        float2 w0 = Ws[(2 * dd) * 32 + lane];
        float2 w1 = Ws[(2 * dd + 1) * 32 + lane];
#pragma unroll
        for (int r = 0; r < 4; r++) {
            float md0 = __shfl_sync(0xffffffffu, m0[r], dd);
            float md1 = __shfl_sync(0xffffffffu, m1[r], dd);
            ls0[r] += md0 * w0.x + md1 * w1.x;
            ls1[r] += md0 * w0.y + md1 * w1.y;
        }
    }

#pragma unroll
    for (int r = 0; r < 4; r++) {
        float s0 = __expf(ls0[r]);
        float s1 = __expf(ls1[r]);
        size_t ix = (size_t)(row0 + r) * 32 + lane;
        __stcs(out_std + ix, make_float2(s0, s1));
        __stcs(out_v1 + ix, make_float2(m0[r] + s0 * na[r].x * VSCALE,
                                        m1[r] + s1 * na[r].y * VSCALE));
        __stcs(out_v2 + ix, make_float2(m0[r] + s0 * nc[r].x * VSCALE,
                                        m1[r] + s1 * nc[r].y * VSCALE));
    }
}

// ---------------- launch ----------------
extern "C" void kernel_launch(void* const* d_in, const int* in_sizes, int n_in,
                              void* d_out, int out_size) {
    const float* user = (const float*)d_in[0];
    const float* item = (const float*)d_in[1];
    const float* W    = (const float*)d_in[2];
    const float* bias = (const float*)d_in[3];
    const int*   rows = (const int*)d_in[4];
    const int*   cols = (const int*)d_in[5];
    const float* vals = (const float*)d_in[6];
    const float* n1   = (const float*)d_in[7];
    const float* n2   = (const float*)d_in[8];

    __half2 *x0, *h1, *h2;
    cudaGetSymbolAddress((void**)&x0, g_x0);
    cudaGetSymbolAddress((void**)&h1, g_h1);
    cudaGetSymbolAddress((void**)&h2, g_h2);
    void* cntp;
    cudaGetSymbolAddress(&cntp, g_cnt);

    float* out = (float*)d_out;
    float2* out_mean = (float2*)out;
    float2* out_std  = (float2*)(out + (size_t)NTOT * DD);
    float2* out_v1   = (float2*)(out + 2 * (size_t)NTOT * DD);
    float2* out_v2   = (float2*)(out + 3 * (size_t)NTOT * DD);

    const int T = 256;
    int nbScan = (NTOT + 1023) / 1024;          // 220
    int nbS23 = (NTOT + 255) / 256;             // 879
    int nbE = (NNZV + T - 1) / T;               // 7813
    int nbCvt = (NTOT * 32 + T * 4 - 1) / (T * 4);  // 7032

    // sort COO -> CSR; fp16 convert fused into the hist launch
    cudaMemsetAsync(cntp, 0, NTOT * sizeof(int));
    k_hist_convert<<<nbE + nbCvt, T>>>(rows, (const float2*)user,
                                       (const float2*)item, nbE);
    k_scan1<<<nbScan, 1024>>>();
    k_scan23<<<nbS23, T>>>();
    k_scatter<<<nbE, T>>>(rows, cols, vals);

    // GCN layers 1-2
    int nbSpmm = (NTOT / 4 + 7) / 8;    // 7032
    k_spmm<<<nbSpmm, T>>>(x0, h1);
    k_spmm<<<nbSpmm, T>>>(h1, h2);

    // layer 3 fused with epilogue
    k_spmm3_epi<<<nbSpmm, T>>>(h1, h2, W, bias,
                               (const float2*)n1, (const float2*)n2,
                               out_mean, out_std, out_v1, out_v2);
}

// round 16
// speedup vs baseline: 1.0543x; 1.0543x over previous
#include <cuda_runtime.h>
#include <cuda_fp16.h>

#define NUSER 150000
#define NITEM 75000
#define NTOT  225000
#define DD    64
#define NNZV  2000000
#define VSCALE 0.01f

// ---------------- static device scratch ----------------
__device__ int   g_cnt[NTOT];
__device__ int   g_inc[NTOT];
__device__ int   g_bsum[256];
__device__ int   g_rowptr[NTOT + 1];
__device__ int   g_wptr[NTOT + 1];
__device__ int2  g_edge[NNZV];                    // {col, val-as-int}
__device__ __half2 g_x0[(size_t)NTOT * 32];       // fused user+item, fp16
__device__ __half2 g_h1[(size_t)NTOT * 32];
__device__ __half2 g_h2[(size_t)NTOT * 32];

// ---------------- histogram ----------------
__global__ void k_hist(const int* __restrict__ rows) {
    int e = blockIdx.x * blockDim.x + threadIdx.x;
    if (e < NNZV) atomicAdd(&g_cnt[__ldcs(rows + e)], 1);
}

// shfl-based block scan, 1024 threads, 2 barriers
__global__ void k_scan1() {
    __shared__ int wsum[32];
    int tid = threadIdx.x;
    int lane = tid & 31;
    int wp = tid >> 5;
    int i = blockIdx.x * 1024 + tid;
    int v = (i < NTOT) ? g_cnt[i] : 0;
#pragma unroll
    for (int off = 1; off < 32; off <<= 1) {
        int t = __shfl_up_sync(0xffffffffu, v, off);
        if (lane >= off) v += t;
    }
    if (lane == 31) wsum[wp] = v;
    __syncthreads();
    if (wp == 0) {
        int s = wsum[lane];
#pragma unroll
        for (int off = 1; off < 32; off <<= 1) {
            int t = __shfl_up_sync(0xffffffffu, s, off);
            if (lane >= off) s += t;
        }
        wsum[lane] = s;
    }
    __syncthreads();
    if (wp > 0) v += wsum[wp - 1];
    if (i < NTOT) g_inc[i] = v;
    if (tid == 1023) g_bsum[blockIdx.x] = v;
}

// merged scan2+scan3: each block (256 thr) shares one 1024-bucket; warp 0
// computes the exclusive prefix of g_bsum over [0, bucket) itself.
__global__ void k_scan23() {
    __shared__ int s_off;
    int tid = threadIdx.x;
    int i = blockIdx.x * 256 + tid;
    int bucket = (blockIdx.x * 256) >> 10;     // same for whole block
    if (tid < 32) {
        int acc = 0;
        for (int j = tid; j < bucket; j += 32) acc += g_bsum[j];
#pragma unroll
        for (int off = 16; off > 0; off >>= 1)
            acc += __shfl_down_sync(0xffffffffu, acc, off);
        if (tid == 0) s_off = acc;
    }
    __syncthreads();
    if (i < NTOT) {
        int val = g_inc[i] + s_off;
        g_rowptr[i + 1] = val;
        g_wptr[i + 1] = val;
        if (i == 0) { g_rowptr[0] = 0; g_wptr[0] = 0; }
    }
}

// fused: scatter (first nbE blocks) + fp32->fp16 convert (remaining blocks)
__global__ void k_scatter_convert(const int* __restrict__ rows,
                                  const int* __restrict__ cols,
                                  const float* __restrict__ vals,
                                  const float2* __restrict__ user,
                                  const float2* __restrict__ item,
                                  int nbE) {
    if ((int)blockIdx.x < nbE) {
        int e = blockIdx.x * blockDim.x + threadIdx.x;
        if (e < NNZV) {
            int r = __ldcs(rows + e);
            int p = atomicAdd(&g_wptr[r], 1);
            g_edge[p] = make_int2(__ldcs(cols + e),
                                  __float_as_int(__ldcs(vals + e)));
        }
    } else {
        int base = (blockIdx.x - nbE) * blockDim.x * 4 + threadIdx.x;
#pragma unroll
        for (int u = 0; u < 4; u++) {
            int i = base + u * blockDim.x;
            if (i < NTOT * 32) {
                float2 v = (i < NUSER * 32) ? __ldcs(user + i)
                                            : __ldcs(item + (i - NUSER * 32));
                g_x0[i] = __floats2half2_rn(v.x, v.y);
            }
        }
    }
}

// ---------------- SpMM layers 1-2: 4 rows per warp, interleaved ----------
__global__ void k_spmm(const __half2* __restrict__ x,
                       __half2* __restrict__ y) {
    int lane = threadIdx.x & 31;
    int warp = threadIdx.x >> 5;
    int wid = blockIdx.x * 8 + warp;
    int row0 = wid * 4;
    if (row0 >= NTOT) return;
    const __half2* xlane = x + lane;

    int4 rp = *reinterpret_cast<const int4*>(&g_rowptr[row0]);
    int r4 = g_rowptr[row0 + 4];
    int p[4] = {rp.x, rp.y, rp.z, rp.w};
    int e[4] = {rp.y, rp.z, rp.w, r4};
    int maxlen = max(max(e[0] - p[0], e[1] - p[1]),
                     max(e[2] - p[2], e[3] - p[3]));

    float ax[4] = {0.f, 0.f, 0.f, 0.f};
    float ay[4] = {0.f, 0.f, 0.f, 0.f};

    for (int it = 0; it < maxlen; it++) {
#pragma unroll
        for (int i = 0; i < 4; i++) {
            int idx = p[i] + it;
            if (idx < e[i]) {
                int2 q = *reinterpret_cast<const int2*>(&g_edge[idx]);
                float vv = __int_as_float(q.y);
                float2 xv = __half22float2(__ldg(xlane + (size_t)q.x * 32));
                ax[i] += vv * xv.x;
                ay[i] += vv * xv.y;
            }
        }
    }

#pragma unroll
    for (int i = 0; i < 4; i++)
        y[(size_t)(row0 + i) * 32 + lane] = __floats2half2_rn(ax[i], ay[i]);
}

// ---------------- fused SpMM layer 3 + epilogue -----------------------------
__global__ void k_spmm3_epi(const __half2* __restrict__ h1,
                            const __half2* __restrict__ h2,
                            const float* __restrict__ W,
                            const float* __restrict__ bias,
                            const float2* __restrict__ n1,
                            const float2* __restrict__ n2,
                            float2* __restrict__ out_mean,
                            float2* __restrict__ out_std,
                            float2* __restrict__ out_v1,
                            float2* __restrict__ out_v2) {
    __shared__ float2 Ws[64 * 32];   // Ws[d*32+l] = {W[d][2l], W[d][2l+1]}
    for (int i = threadIdx.x; i < 64 * 32; i += blockDim.x) {
        int d = i >> 5, l = i & 31;
        Ws[i] = *reinterpret_cast<const float2*>(W + d * 64 + 2 * l);
    }
    __syncthreads();

    int lane = threadIdx.x & 31;
    int warp = threadIdx.x >> 5;
    int wid = blockIdx.x * 8 + warp;
    int row0 = wid * 4;
    if (row0 >= NTOT) return;
    const __half2* xlane = h2 + lane;

    int4 rp = *reinterpret_cast<const int4*>(&g_rowptr[row0]);
    int r4 = g_rowptr[row0 + 4];
    int p[4] = {rp.x, rp.y, rp.z, rp.w};
    int e[4] = {rp.y, rp.z, rp.w, r4};
    int maxlen = max(max(e[0] - p[0], e[1] - p[1]),
                     max(e[2] - p[2], e[3] - p[3]));

    float ax[4] = {0.f, 0.f, 0.f, 0.f};
    float ay[4] = {0.f, 0.f, 0.f, 0.f};
    for (int it = 0; it < maxlen; it++) {
#pragma unroll
        for (int i = 0; i < 4; i++) {
            int idx = p[i] + it;
            if (idx < e[i]) {
                int2 q = *reinterpret_cast<const int2*>(&g_edge[idx]);
                float vv = __int_as_float(q.y);
                float2 xv = __half22float2(__ldg(xlane + (size_t)q.x * 32));
                ax[i] += vv * xv.x;
                ay[i] += vv * xv.y;
            }
        }
    }

    // ---- preload noise (overlap DRAM latency with GEMM below) ----
    float2 na[4], nc[4];
#pragma unroll
    for (int r = 0; r < 4; r++) {
        size_t ix = (size_t)(row0 + r) * 32 + lane;
        na[r] = __ldcs(n1 + ix);
        nc[r] = __ldcs(n2 + ix);
    }

    // ---- mean (store immediately) ----
    float2 b = __ldg(reinterpret_cast<const float2*>(bias) + lane);
    float m0[4], m1[4], ls0[4], ls1[4];
#pragma unroll
    for (int r = 0; r < 4; r++) {
        size_t ix = (size_t)(row0 + r) * 32 + lane;
        float2 a1 = __half22float2(__ldg(h1 + ix));
        float2 a2 = __half22float2(__ldg(h2 + ix));
        m0[r] = (a1.x + a2.x + ax[r]) * (1.f / 3.f);
        m1[r] = (a1.y + a2.y + ay[r]) * (1.f / 3.f);
        __stcs(out_mean + ix, make_float2(m0[r], m1[r]));
        ls0[r] = b.x;
        ls1[r] = b.y;
    }

    // ---- 64x64 GEMM via shfl ----
#pragma unroll 4
    for (int dd = 0; dd < 32; dd++) {
        float2 w0 = Ws[(2 * dd) * 32 + lane];
        float2 w1 = Ws[(2 * dd + 1) * 32 + lane];
#pragma unroll
        for (int r = 0; r < 4; r++) {
            float md0 = __shfl_sync(0xffffffffu, m0[r], dd);
            float md1 = __shfl_sync(0xffffffffu, m1[r], dd);
            ls0[r] += md0 * w0.x + md1 * w1.x;
            ls1[r] += md0 * w0.y + md1 * w1.y;
        }
    }

#pragma unroll
    for (int r = 0; r < 4; r++) {
        float s0 = __expf(ls0[r]);
        float s1 = __expf(ls1[r]);
        size_t ix = (size_t)(row0 + r) * 32 + lane;
        __stcs(out_std + ix, make_float2(s0, s1));
        __stcs(out_v1 + ix, make_float2(m0[r] + s0 * na[r].x * VSCALE,
                                        m1[r] + s1 * na[r].y * VSCALE));
        __stcs(out_v2 + ix, make_float2(m0[r] + s0 * nc[r].x * VSCALE,
                                        m1[r] + s1 * nc[r].y * VSCALE));
    }
}

// ---------------- launch ----------------
extern "C" void kernel_launch(void* const* d_in, const int* in_sizes, int n_in,
                              void* d_out, int out_size) {
    const float* user = (const float*)d_in[0];
    const float* item = (const float*)d_in[1];
    const float* W    = (const float*)d_in[2];
    const float* bias = (const float*)d_in[3];
    const int*   rows = (const int*)d_in[4];
    const int*   cols = (const int*)d_in[5];
    const float* vals = (const float*)d_in[6];
    const float* n1   = (const float*)d_in[7];
    const float* n2   = (const float*)d_in[8];

    __half2 *x0, *h1, *h2;
    cudaGetSymbolAddress((void**)&x0, g_x0);
    cudaGetSymbolAddress((void**)&h1, g_h1);
    cudaGetSymbolAddress((void**)&h2, g_h2);
    void* cntp;
    cudaGetSymbolAddress(&cntp, g_cnt);

    float* out = (float*)d_out;
    float2* out_mean = (float2*)out;
    float2* out_std  = (float2*)(out + (size_t)NTOT * DD);
    float2* out_v1   = (float2*)(out + 2 * (size_t)NTOT * DD);
    float2* out_v2   = (float2*)(out + 3 * (size_t)NTOT * DD);

    const int T = 256;
    int nbScan = (NTOT + 1023) / 1024;          // 220
    int nbS23 = (NTOT + 255) / 256;             // 879
    int nbE = (NNZV + T - 1) / T;               // 7813
    int nbCvt = (NTOT * 32 + T * 4 - 1) / (T * 4);  // 7032

    // sort COO -> CSR, convert fused into scatter launch
    cudaMemsetAsync(cntp, 0, NTOT * sizeof(int));
    k_hist<<<nbE, T>>>(rows);
    k_scan1<<<nbScan, 1024>>>();
    k_scan23<<<nbS23, T>>>();
    k_scatter_convert<<<nbE + nbCvt, T>>>(rows, cols, vals,
                                          (const float2*)user,
                                          (const float2*)item, nbE);

    // GCN layers 1-2
    int nbSpmm = (NTOT / 4 + 7) / 8;    // 7032
    k_spmm<<<nbSpmm, T>>>(x0, h1);
    k_spmm<<<nbSpmm, T>>>(h1, h2);

    // layer 3 fused with epilogue
    k_spmm3_epi<<<nbSpmm, T>>>(h1, h2, W, bias,
                               (const float2*)n1, (const float2*)n2,
                               out_mean, out_std, out_v1, out_v2);
}